// round 4
// baseline (speedup 1.0000x reference)
#include <cuda_runtime.h>
#include <cuda_bf16.h>
#include <cstdint>

#define LSEQ 4096
#define DM   256
#define BMAX 4
#define TM   128
#define TN   128
#define NKT  (LSEQ / TN)     // 32
#define NTHR 256

// -------- scratch globals --------
__device__ __align__(16) __nv_bfloat16 g_xb[BMAX * LSEQ * DM];   // [b][l][d] bf16
__device__ __align__(16) __nv_bfloat16 g_ebias[BMAX * LSEQ];     // e^{-||x_l||^2/2}

// -------- smem byte offsets --------
#define QSOFF  0            // Q [128][256] bf16, 512B rows, group swz g^(r&7)
#define KOFF   32768        // 2 x 65536 : K tile [128][256] bf16, same layout
#define POFF   163840       // P [128][128] bf16, 256B rows, group swz g^(r&15)
#define EBOFF  196608       // 2 x 256B ebias tiles (128 bf16)
#define SMEM_BYTES 197120

// ---------------- asm helpers ----------------
__device__ __forceinline__ uint32_t smem_u32(const void* p) {
    uint32_t a;
    asm("{ .reg .u64 t; cvta.to.shared.u64 t, %1; cvt.u32.u64 %0, t; }" : "=r"(a) : "l"(p));
    return a;
}
__device__ __forceinline__ void cp_async16(uint32_t dst, const void* src) {
    asm volatile("cp.async.cg.shared.global [%0], [%1], 16;" :: "r"(dst), "l"(src) : "memory");
}
__device__ __forceinline__ void cp_commit() { asm volatile("cp.async.commit_group;" ::: "memory"); }
__device__ __forceinline__ void cp_wait0()  { asm volatile("cp.async.wait_group 0;" ::: "memory"); }

__device__ __forceinline__ void ldsm_x4(uint32_t addr, uint32_t r[4]) {
    asm volatile("ldmatrix.sync.aligned.m8n8.x4.shared.b16 {%0,%1,%2,%3}, [%4];"
        : "=r"(r[0]), "=r"(r[1]), "=r"(r[2]), "=r"(r[3]) : "r"(addr));
}
__device__ __forceinline__ void ldsm_x4t(uint32_t addr, uint32_t r[4]) {
    asm volatile("ldmatrix.sync.aligned.m8n8.x4.trans.shared.b16 {%0,%1,%2,%3}, [%4];"
        : "=r"(r[0]), "=r"(r[1]), "=r"(r[2]), "=r"(r[3]) : "r"(addr));
}
__device__ __forceinline__ void mma16816(float c[4], const uint32_t a[4],
                                         uint32_t b0, uint32_t b1) {
    asm volatile("mma.sync.aligned.m16n8k16.row.col.f32.bf16.bf16.f32 "
        "{%0,%1,%2,%3}, {%4,%5,%6,%7}, {%8,%9}, {%0,%1,%2,%3};"
        : "+f"(c[0]), "+f"(c[1]), "+f"(c[2]), "+f"(c[3])
        : "r"(a[0]), "r"(a[1]), "r"(a[2]), "r"(a[3]), "r"(b0), "r"(b1));
}
__device__ __forceinline__ uint32_t pack2bf(float lo, float hi) {
    uint32_t r;
    asm("cvt.rn.bf16x2.f32 %0, %1, %2;" : "=r"(r) : "f"(hi), "f"(lo));
    return r;
}
__device__ __forceinline__ uint32_t hfma2(uint32_t a, uint32_t b, uint32_t c) {
    uint32_t d;
    asm("fma.rn.bf16x2 %0, %1, %2, %3;" : "=r"(d) : "r"(a), "r"(b), "r"(c));
    return d;
}
__device__ __forceinline__ uint32_t hmul2(uint32_t a, uint32_t b) {
    uint32_t d;
    asm("mul.rn.bf16x2 %0, %1, %2;" : "=r"(d) : "r"(a), "r"(b));
    return d;
}
__device__ __forceinline__ void sts32(uint32_t a, uint32_t v) {
    asm volatile("st.shared.b32 [%0], %1;" :: "r"(a), "r"(v) : "memory");
}

// ================= pre-pass: x f32 -> bf16, ebias = e^{-||x||^2/2} =================
__global__ void conv_bias_kernel(const float* __restrict__ x) {
    int row  = blockIdx.x * 8 + (threadIdx.x >> 5);
    int lane = threadIdx.x & 31;
    const float* xr = x + (size_t)row * DM + lane * 8;
    float4 a = *reinterpret_cast<const float4*>(xr);
    float4 b = *reinterpret_cast<const float4*>(xr + 4);
    uint4 v;
    v.x = pack2bf(a.x, a.y); v.y = pack2bf(a.z, a.w);
    v.z = pack2bf(b.x, b.y); v.w = pack2bf(b.z, b.w);
    reinterpret_cast<uint4*>(g_xb + (size_t)row * DM)[lane] = v;
    float s = a.x*a.x + a.y*a.y + a.z*a.z + a.w*a.w
            + b.x*b.x + b.y*b.y + b.z*b.z + b.w*b.w;
    #pragma unroll
    for (int m = 16; m > 0; m >>= 1) s += __shfl_xor_sync(0xffffffffu, s, m);
    if (lane == 0) g_ebias[row] = __float2bfloat16(__expf(-0.5f * s));
}

// ================= main flash kernel =================
__global__ __launch_bounds__(NTHR, 1)
void tpe_flash2_kernel(const float* __restrict__ x, float* __restrict__ out)
{
    extern __shared__ char smem[];
    const uint32_t sbase = smem_u32(smem);
    const int tid  = threadIdx.x;
    const int wid  = tid >> 5;
    const int lane = tid & 31;
    const int b    = blockIdx.y;
    const int row0 = blockIdx.x * TM;

    const int wm1 = wid & 3, wn1 = wid >> 2;      // GEMM1: 4m x 2n
    const int wm2 = wid & 1, wd2 = wid >> 1;      // GEMM2: 2m x 4d

    const int lr = lane & 15, lh = lane >> 4;

    const __nv_bfloat16* xb = g_xb + (size_t)b * LSEQ * DM;
    const __nv_bfloat16* eb_g = g_ebias + (size_t)b * LSEQ;

    // ---- prologue: Q + K[0] + eb[0] ----
    #pragma unroll
    for (int it = 0; it < 16; it++) {
        int idx = it * NTHR + tid;
        int r = idx >> 5, g = idx & 31;
        cp_async16(sbase + QSOFF + r * 512 + (((uint32_t)g ^ (r & 7)) << 4),
                   xb + (size_t)(row0 + r) * DM + g * 8);
    }
    #pragma unroll
    for (int it = 0; it < 16; it++) {
        int idx = it * NTHR + tid;
        int r = idx >> 5, g = idx & 31;
        cp_async16(sbase + KOFF + r * 512 + (((uint32_t)g ^ (r & 7)) << 4),
                   xb + (size_t)r * DM + g * 8);
    }
    if (tid < 16)
        cp_async16(sbase + EBOFF + tid * 16, eb_g + tid * 8);
    cp_commit();
    cp_wait0();
    __syncthreads();

    // persistent accumulators (GEMM2 view)
    float oc[4][8][4];
    #pragma unroll
    for (int mt = 0; mt < 4; mt++)
        #pragma unroll
        for (int f = 0; f < 8; f++)
            #pragma unroll
            for (int q = 0; q < 4; q++) oc[mt][f][q] = 0.f;
    float dcc[4][4];
    #pragma unroll
    for (int mt = 0; mt < 4; mt++)
        #pragma unroll
        for (int q = 0; q < 4; q++) dcc[mt][q] = 0.f;

    const uint32_t ONE2 = 0x3F803F80u;
    const uint32_t C6   = pack2bf(1.f/6.f, 1.f/6.f);
    const uint32_t CH   = pack2bf(0.5f, 0.5f);
    const uint32_t bone = ((lane >> 2) == 0) ? ONE2 : 0u;

    // ================= key-tile loop =================
    for (int t = 0; t < NKT; t++) {
        const int slot = t & 1;
        const uint32_t Kb = sbase + KOFF + slot * 65536;

        // ---- GEMM1: S[32 rows][64 keys] per warp ----
        float sc[2][8][4];
        #pragma unroll
        for (int mt = 0; mt < 2; mt++)
            #pragma unroll
            for (int f = 0; f < 8; f++)
                #pragma unroll
                for (int q = 0; q < 4; q++) sc[mt][f][q] = 0.f;

        #pragma unroll
        for (int k = 0; k < 16; k++) {
            uint32_t aq[2][4];
            #pragma unroll
            for (int mt = 0; mt < 2; mt++) {
                int ar = 32 * wm1 + 16 * mt + lr;
                uint32_t phys = (uint32_t)((2 * k + lh) ^ (ar & 7));
                ldsm_x4(sbase + QSOFF + ar * 512 + (phys << 4), aq[mt]);
            }
            #pragma unroll
            for (int nt = 0; nt < 4; nt++) {
                int rn = 64 * wn1 + 16 * nt + lr;
                uint32_t phys = (uint32_t)((2 * k + lh) ^ (rn & 7));
                uint32_t bk[4];
                ldsm_x4(Kb + rn * 512 + (phys << 4), bk);
                #pragma unroll
                for (int mt = 0; mt < 2; mt++) {
                    mma16816(sc[mt][2*nt],     aq[mt], bk[0], bk[2]);
                    mma16816(sc[mt][2*nt + 1], aq[mt], bk[1], bk[3]);
                }
            }
        }

        // ---- softmax + P store ----
        {
            const uint32_t ebb = sbase + EBOFF + slot * 256;
            #pragma unroll
            for (int mt = 0; mt < 2; mt++) {
                int r0 = 32 * wm1 + 16 * mt + (lane >> 2);
                int r1 = r0 + 8;
                #pragma unroll
                for (int f = 0; f < 8; f++) {
                    int n = 64 * wn1 + 8 * f + 2 * (lane & 3);
                    uint32_t eb;
                    asm volatile("ld.shared.b32 %0, [%1];" : "=r"(eb) : "r"(ebb + n * 2));
                    uint32_t v01 = pack2bf(sc[mt][f][0], sc[mt][f][1]);
                    uint32_t v23 = pack2bf(sc[mt][f][2], sc[mt][f][3]);
                    uint32_t h0 = hfma2(v01, C6, CH);
                    h0 = hfma2(h0, v01, ONE2);
                    h0 = hfma2(h0, v01, ONE2);
                    uint32_t h1 = hfma2(v23, C6, CH);
                    h1 = hfma2(h1, v23, ONE2);
                    h1 = hfma2(h1, v23, ONE2);
                    uint32_t p0 = hmul2(h0, eb);
                    uint32_t p1 = hmul2(h1, eb);
                    uint32_t g = (uint32_t)(8 * wn1 + f);
                    sts32(sbase + POFF + r0 * 256 + ((g ^ (r0 & 15)) << 4) + (lane & 3) * 4, p0);
                    sts32(sbase + POFF + r1 * 256 + ((g ^ (r1 & 15)) << 4) + (lane & 3) * 4, p1);
                }
            }
        }
        __syncthreads();                       // P visible; K[slot^1] free

        // ---- prefetch next tile ----
        if (t + 1 < NKT) {
            const int ns = slot ^ 1;
            #pragma unroll
            for (int it = 0; it < 16; it++) {
                int idx = it * NTHR + tid;
                int r = idx >> 5, g = idx & 31;
                cp_async16(sbase + KOFF + ns * 65536 + r * 512 +
                               (((uint32_t)g ^ (r & 7)) << 4),
                           xb + (size_t)((t + 1) * TN + r) * DM + g * 8);
            }
            if (tid < 16)
                cp_async16(sbase + EBOFF + ns * 256 + tid * 16,
                           eb_g + (t + 1) * TN + tid * 8);
            cp_commit();
        }

        // ---- GEMM2: O[64 m][64 d] += P . V, den += P . 1 ----
        {
            const uint32_t Pb = sbase + POFF;
            #pragma unroll
            for (int kk = 0; kk < 8; kk++) {
                uint32_t pa[4][4];
                #pragma unroll
                for (int mt = 0; mt < 4; mt++) {
                    int pr = 64 * wm2 + 16 * mt + lr;
                    uint32_t phys = (uint32_t)((2 * kk + lh) ^ (pr & 15));
                    ldsm_x4(Pb + pr * 256 + (phys << 4), pa[mt]);
                    mma16816(dcc[mt], pa[mt], bone, bone);
                }
                #pragma unroll
                for (int bn = 0; bn < 4; bn++) {
                    int rv = 16 * kk + lr;
                    int c16 = 4 * wd2 + bn;
                    uint32_t phys = (uint32_t)((2 * c16 + lh) ^ (rv & 7));
                    uint32_t bv[4];
                    ldsm_x4t(Kb + rv * 512 + (phys << 4), bv);
                    #pragma unroll
                    for (int mt = 0; mt < 4; mt++) {
                        mma16816(oc[mt][2*bn],     pa[mt], bv[0], bv[1]);
                        mma16816(oc[mt][2*bn + 1], pa[mt], bv[2], bv[3]);
                    }
                }
            }
        }

        if (t + 1 < NKT) {
            cp_wait0();
            __syncthreads();                   // K[slot^1] ready for GEMM1(t+1)
        }
    }

    // ================= epilogue: out = x + pe + O/den =================
    const float C_FREQ  = -0.035977892078032f;     // -ln(1e4)/256
    const float INV_2PI =  0.15915494309189535f;
    const float PI2_HI  =  6.28125f;
    const float PI2_LO  =  1.9353071795864769e-3f;

    #pragma unroll
    for (int mt = 0; mt < 4; mt++) {
        float dlo = __shfl_sync(0xffffffffu, dcc[mt][0], lane & ~3);
        float dhi = __shfl_sync(0xffffffffu, dcc[mt][2], lane & ~3);
        float ilo = 1.f / dlo, ihi = 1.f / dhi;
        const int rlo = row0 + 64 * wm2 + 16 * mt + (lane >> 2);
        const int rhi = rlo + 8;
        const float* xlo = x   + ((size_t)b * LSEQ + rlo) * DM;
        const float* xhi = x   + ((size_t)b * LSEQ + rhi) * DM;
        float*       olo = out + ((size_t)b * LSEQ + rlo) * DM;
        float*       ohi = out + ((size_t)b * LSEQ + rhi) * DM;
        #pragma unroll
        for (int f = 0; f < 8; f++) {
            int d0 = 64 * wd2 + 8 * f + 2 * (lane & 3);
            float w = __expf(C_FREQ * (float)d0);
            {
                float ang = (float)rlo * w;
                float k = rintf(ang * INV_2PI);
                float rr = fmaf(-k, PI2_HI, ang); rr = fmaf(-k, PI2_LO, rr);
                float2 xv = *reinterpret_cast<const float2*>(xlo + d0);
                float2 ov;
                ov.x = xv.x + __sinf(rr) + oc[mt][f][0] * ilo;
                ov.y = xv.y + __cosf(rr) + oc[mt][f][1] * ilo;
                *reinterpret_cast<float2*>(olo + d0) = ov;
            }
            {
                float ang = (float)rhi * w;
                float k = rintf(ang * INV_2PI);
                float rr = fmaf(-k, PI2_HI, ang); rr = fmaf(-k, PI2_LO, rr);
                float2 xv = *reinterpret_cast<const float2*>(xhi + d0);
                float2 ov;
                ov.x = xv.x + __sinf(rr) + oc[mt][f][2] * ihi;
                ov.y = xv.y + __cosf(rr) + oc[mt][f][3] * ihi;
                *reinterpret_cast<float2*>(ohi + d0) = ov;
            }
        }
    }
}

// ================= launcher =================
extern "C" void kernel_launch(void* const* d_in, const int* in_sizes, int n_in,
                              void* d_out, int out_size)
{
    const float* x = (const float*)d_in[0];
    float* out = (float*)d_out;
    const int B = in_sizes[0] / (LSEQ * DM);

    conv_bias_kernel<<<B * LSEQ / 8, 256>>>(x);

    cudaFuncSetAttribute(tpe_flash2_kernel,
                         cudaFuncAttributeMaxDynamicSharedMemorySize, SMEM_BYTES);
    tpe_flash2_kernel<<<dim3(LSEQ / TM, B), NTHR, SMEM_BYTES>>>(x, out);
}

// round 5
// speedup vs baseline: 1.0143x; 1.0143x over previous
#include <cuda_runtime.h>
#include <cuda_bf16.h>
#include <cstdint>

#define LSEQ 4096
#define DM   256
#define BMAX 4
#define TM   128
#define TN   64
#define NKT  (LSEQ / TN)     // 64
#define NTHR 256

// -------- scratch globals --------
__device__ __align__(16) __nv_bfloat16 g_xb[BMAX * LSEQ * DM];   // [b][l][d] bf16
__device__ __align__(16) __nv_bfloat16 g_ebias[BMAX * LSEQ];     // e^{-||x_l||^2/2}

// -------- smem byte offsets (no aliasing this time: Q is 65536 B) --------
#define QSOFF  0              // Q [128 rows][512B], group swz g^(r&7)
#define KOFF   65536          // 2 x 32768 : K tile [64 rows][512B], same swz
#define POFF   131072         // P [128 rows][128B] bf16, group swz g^(r&7)
#define EBOFF  147456         // 2 x 128B ebias tiles (64 bf16)
#define SMEM_BYTES 147712

// ---------------- asm helpers ----------------
__device__ __forceinline__ uint32_t smem_u32(const void* p) {
    uint32_t a;
    asm("{ .reg .u64 t; cvta.to.shared.u64 t, %1; cvt.u32.u64 %0, t; }" : "=r"(a) : "l"(p));
    return a;
}
__device__ __forceinline__ void cp_async16(uint32_t dst, const void* src) {
    asm volatile("cp.async.cg.shared.global [%0], [%1], 16;" :: "r"(dst), "l"(src) : "memory");
}
__device__ __forceinline__ void cp_commit() { asm volatile("cp.async.commit_group;" ::: "memory"); }
__device__ __forceinline__ void cp_wait0()  { asm volatile("cp.async.wait_group 0;" ::: "memory"); }

__device__ __forceinline__ void ldsm_x4(uint32_t addr, uint32_t r[4]) {
    asm volatile("ldmatrix.sync.aligned.m8n8.x4.shared.b16 {%0,%1,%2,%3}, [%4];"
        : "=r"(r[0]), "=r"(r[1]), "=r"(r[2]), "=r"(r[3]) : "r"(addr));
}
__device__ __forceinline__ void ldsm_x4t(uint32_t addr, uint32_t r[4]) {
    asm volatile("ldmatrix.sync.aligned.m8n8.x4.trans.shared.b16 {%0,%1,%2,%3}, [%4];"
        : "=r"(r[0]), "=r"(r[1]), "=r"(r[2]), "=r"(r[3]) : "r"(addr));
}
__device__ __forceinline__ void mma16816(float c[4], const uint32_t a[4],
                                         uint32_t b0, uint32_t b1) {
    asm volatile("mma.sync.aligned.m16n8k16.row.col.f32.bf16.bf16.f32 "
        "{%0,%1,%2,%3}, {%4,%5,%6,%7}, {%8,%9}, {%0,%1,%2,%3};"
        : "+f"(c[0]), "+f"(c[1]), "+f"(c[2]), "+f"(c[3])
        : "r"(a[0]), "r"(a[1]), "r"(a[2]), "r"(a[3]), "r"(b0), "r"(b1));
}
__device__ __forceinline__ uint32_t pack2bf(float lo, float hi) {
    uint32_t r;
    asm("cvt.rn.bf16x2.f32 %0, %1, %2;" : "=r"(r) : "f"(hi), "f"(lo));
    return r;
}
__device__ __forceinline__ uint32_t hfma2(uint32_t a, uint32_t b, uint32_t c) {
    uint32_t d;
    asm("fma.rn.bf16x2 %0, %1, %2, %3;" : "=r"(d) : "r"(a), "r"(b), "r"(c));
    return d;
}
__device__ __forceinline__ uint32_t hmul2(uint32_t a, uint32_t b) {
    uint32_t d;
    asm("mul.rn.bf16x2 %0, %1, %2;" : "=r"(d) : "r"(a), "r"(b));
    return d;
}
__device__ __forceinline__ void sts32(uint32_t a, uint32_t v) {
    asm volatile("st.shared.b32 [%0], %1;" :: "r"(a), "r"(v) : "memory");
}

// ================= pre-pass: x f32 -> bf16, ebias = e^{-||x||^2/2} =================
__global__ void conv_bias_kernel(const float* __restrict__ x) {
    int row  = blockIdx.x * 8 + (threadIdx.x >> 5);
    int lane = threadIdx.x & 31;
    const float* xr = x + (size_t)row * DM + lane * 8;
    float4 a = *reinterpret_cast<const float4*>(xr);
    float4 b = *reinterpret_cast<const float4*>(xr + 4);
    uint4 v;
    v.x = pack2bf(a.x, a.y); v.y = pack2bf(a.z, a.w);
    v.z = pack2bf(b.x, b.y); v.w = pack2bf(b.z, b.w);
    reinterpret_cast<uint4*>(g_xb + (size_t)row * DM)[lane] = v;
    float s = a.x*a.x + a.y*a.y + a.z*a.z + a.w*a.w
            + b.x*b.x + b.y*b.y + b.z*b.z + b.w*b.w;
    #pragma unroll
    for (int m = 16; m > 0; m >>= 1) s += __shfl_xor_sync(0xffffffffu, s, m);
    if (lane == 0) g_ebias[row] = __float2bfloat16(__expf(-0.5f * s));
}

// ================= main flash kernel =================
__global__ __launch_bounds__(NTHR, 1)
void tpe_flash3_kernel(const float* __restrict__ x, float* __restrict__ out)
{
    extern __shared__ char smem[];
    const uint32_t sbase = smem_u32(smem);
    const int tid  = threadIdx.x;
    const int wid  = tid >> 5;
    const int lane = tid & 31;
    const int b    = blockIdx.y;
    const int row0 = blockIdx.x * TM;

    const int wm = wid & 3;          // m-group: rows 32*wm .. +31
    const int wn = wid >> 2;         // key half for GEMM1, d half for GEMM2

    const int lr = lane & 15, lh = lane >> 4;
    const int lq = lane >> 2, lc = lane & 3;

    const __nv_bfloat16* xb   = g_xb + (size_t)b * LSEQ * DM;
    const __nv_bfloat16* eb_g = g_ebias + (size_t)b * LSEQ;

    // ---- prologue: Q + K[0] + eb[0] ----
    #pragma unroll
    for (int it = 0; it < 16; it++) {
        int idx = it * NTHR + tid;
        int r = idx >> 5, g = idx & 31;
        cp_async16(sbase + QSOFF + r * 512 + (((uint32_t)g ^ (r & 7)) << 4),
                   xb + (size_t)(row0 + r) * DM + g * 8);
    }
    #pragma unroll
    for (int it = 0; it < 8; it++) {
        int idx = it * NTHR + tid;
        int r = idx >> 5, g = idx & 31;
        cp_async16(sbase + KOFF + r * 512 + (((uint32_t)g ^ (r & 7)) << 4),
                   xb + (size_t)r * DM + g * 8);
    }
    if (tid < 8)
        cp_async16(sbase + EBOFF + tid * 16, eb_g + tid * 8);
    cp_commit();
    cp_wait0();
    __syncthreads();

    // persistent accumulators: O rows 32wm+16mt+{lq, lq+8}, d = 128wn + 8ff + 2lc
    float oc[2][16][4];
    #pragma unroll
    for (int mt = 0; mt < 2; mt++)
        #pragma unroll
        for (int f = 0; f < 16; f++)
            #pragma unroll
            for (int q = 0; q < 4; q++) oc[mt][f][q] = 0.f;
    float dcc[2][4];
    #pragma unroll
    for (int mt = 0; mt < 2; mt++)
        #pragma unroll
        for (int q = 0; q < 4; q++) dcc[mt][q] = 0.f;

    const uint32_t ONE2 = 0x3F803F80u;
    const uint32_t C6   = pack2bf(1.f/6.f, 1.f/6.f);
    const uint32_t CH   = pack2bf(0.5f, 0.5f);
    const uint32_t bone = (lq == 0) ? ONE2 : 0u;

    // ================= key-tile loop =================
    for (int t = 0; t < NKT; t++) {
        const int slot = t & 1;
        const uint32_t Kb = sbase + KOFF + slot * 32768;

        // ---- GEMM1: S[32 rows][32 keys] per warp ----
        float sc[2][4][4];
        #pragma unroll
        for (int mt = 0; mt < 2; mt++)
            #pragma unroll
            for (int f = 0; f < 4; f++)
                #pragma unroll
                for (int q = 0; q < 4; q++) sc[mt][f][q] = 0.f;

        #pragma unroll
        for (int k = 0; k < 16; k++) {
            uint32_t aq[2][4];
            #pragma unroll
            for (int mt = 0; mt < 2; mt++) {
                int ar = 32 * wm + 16 * mt + lr;
                uint32_t phys = (uint32_t)((2 * k + lh) ^ (ar & 7));
                ldsm_x4(sbase + QSOFF + ar * 512 + (phys << 4), aq[mt]);
            }
            #pragma unroll
            for (int nt = 0; nt < 2; nt++) {
                int rn = 32 * wn + 16 * nt + lr;
                uint32_t phys = (uint32_t)((2 * k + lh) ^ (rn & 7));
                uint32_t bk[4];
                ldsm_x4(Kb + rn * 512 + (phys << 4), bk);
                #pragma unroll
                for (int mt = 0; mt < 2; mt++) {
                    mma16816(sc[mt][2*nt],     aq[mt], bk[0], bk[2]);
                    mma16816(sc[mt][2*nt + 1], aq[mt], bk[1], bk[3]);
                }
            }
        }

        // ---- softmax -> P (own half in regs as GEMM2 A-frags) + store to smem ----
        uint32_t pkA[2][2][4];      // [mt][local k16 block][frag]
        {
            const uint32_t ebb = sbase + EBOFF + slot * 128;
            #pragma unroll
            for (int mt = 0; mt < 2; mt++) {
                int r0 = 32 * wm + 16 * mt + lq;
                int r1 = r0 + 8;
                #pragma unroll
                for (int f = 0; f < 4; f++) {
                    int n = 32 * wn + 16 * (f >> 1) + 8 * (f & 1) + 2 * lc;
                    uint32_t eb;
                    asm volatile("ld.shared.b32 %0, [%1];" : "=r"(eb) : "r"(ebb + n * 2));
                    uint32_t v01 = pack2bf(sc[mt][f][0], sc[mt][f][1]);
                    uint32_t v23 = pack2bf(sc[mt][f][2], sc[mt][f][3]);
                    uint32_t h0 = hfma2(v01, C6, CH);
                    h0 = hfma2(h0, v01, ONE2);
                    h0 = hfma2(h0, v01, ONE2);
                    uint32_t h1 = hfma2(v23, C6, CH);
                    h1 = hfma2(h1, v23, ONE2);
                    h1 = hfma2(h1, v23, ONE2);
                    uint32_t p0 = hmul2(h0, eb);   // rows r0, cols n..n+1
                    uint32_t p1 = hmul2(h1, eb);   // rows r1
                    int KB = f >> 1, hh = f & 1;
                    pkA[mt][KB][2 * hh]     = p0;
                    pkA[mt][KB][2 * hh + 1] = p1;
                    uint32_t g3 = (uint32_t)(4 * wn + f);   // n>>3
                    sts32(sbase + POFF + r0 * 128 + ((g3 ^ (r0 & 7)) << 4) + lc * 4, p0);
                    sts32(sbase + POFF + r1 * 128 + ((g3 ^ (r1 & 7)) << 4) + lc * 4, p1);
                }
            }
        }
        __syncthreads();           // P visible to partner warp

        // ---- prefetch next K tile into the other slot ----
        if (t + 1 < NKT) {
            const int ns = slot ^ 1;
            #pragma unroll
            for (int it = 0; it < 8; it++) {
                int idx = it * NTHR + tid;
                int r = idx >> 5, g = idx & 31;
                cp_async16(sbase + KOFF + ns * 32768 + r * 512 +
                               (((uint32_t)g ^ (r & 7)) << 4),
                           xb + (size_t)((t + 1) * TN + r) * DM + g * 8);
            }
            if (tid < 8)
                cp_async16(sbase + EBOFF + ns * 128 + tid * 16,
                           eb_g + (t + 1) * TN + tid * 8);
            cp_commit();
        }

        // ---- GEMM2: O[32][128] += P[32][64] . V[64][128wn..], den += P . 1 ----
        #pragma unroll
        for (int kk = 0; kk < 4; kk++) {
            uint32_t pa[2][4];
            #pragma unroll
            for (int mt = 0; mt < 2; mt++) {
                if ((kk >> 1) == wn) {
                    pa[mt][0] = pkA[mt][kk & 1][0];
                    pa[mt][1] = pkA[mt][kk & 1][1];
                    pa[mt][2] = pkA[mt][kk & 1][2];
                    pa[mt][3] = pkA[mt][kk & 1][3];
                } else {
                    int pr = 32 * wm + 16 * mt + lr;
                    uint32_t phys = (uint32_t)((2 * kk + lh) ^ (pr & 7));
                    ldsm_x4(sbase + POFF + pr * 128 + (phys << 4), pa[mt]);
                }
                mma16816(dcc[mt], pa[mt], bone, bone);
            }
            int rv = 16 * kk + lr;
            uint32_t vswz = (uint32_t)(rv & 7);
            uint32_t vb = Kb + rv * 512;
            #pragma unroll
            for (int bn = 0; bn < 8; bn++) {
                int c16 = 8 * wn + bn;
                uint32_t phys = (uint32_t)((2 * c16 + lh) ^ vswz);
                uint32_t bv[4];
                ldsm_x4t(vb + (phys << 4), bv);
                #pragma unroll
                for (int mt = 0; mt < 2; mt++) {
                    mma16816(oc[mt][2*bn],     pa[mt], bv[0], bv[1]);
                    mma16816(oc[mt][2*bn + 1], pa[mt], bv[2], bv[3]);
                }
            }
        }

        if (t + 1 < NKT) {
            cp_wait0();
            __syncthreads();       // next K ready; P region free for next tile
        }
    }

    // ================= epilogue: out = x + pe + O/den =================
    const float C_FREQ  = -0.035977892078032f;     // -ln(1e4)/256
    const float INV_2PI =  0.15915494309189535f;
    const float PI2_HI  =  6.28125f;
    const float PI2_LO  =  1.9353071795864769e-3f;

    #pragma unroll
    for (int mt = 0; mt < 2; mt++) {
        float dlo = __shfl_sync(0xffffffffu, dcc[mt][0], lane & ~3);
        float dhi = __shfl_sync(0xffffffffu, dcc[mt][2], lane & ~3);
        float ilo = 1.f / dlo, ihi = 1.f / dhi;
        const int rlo = row0 + 32 * wm + 16 * mt + lq;
        const int rhi = rlo + 8;
        const float* xlo = x   + ((size_t)b * LSEQ + rlo) * DM;
        const float* xhi = x   + ((size_t)b * LSEQ + rhi) * DM;
        float*       olo = out + ((size_t)b * LSEQ + rlo) * DM;
        float*       ohi = out + ((size_t)b * LSEQ + rhi) * DM;
        #pragma unroll
        for (int f = 0; f < 16; f++) {
            int d0 = 128 * wn + 8 * f + 2 * lc;
            float w = __expf(C_FREQ * (float)d0);
            {
                float ang = (float)rlo * w;
                float k = rintf(ang * INV_2PI);
                float rr = fmaf(-k, PI2_HI, ang); rr = fmaf(-k, PI2_LO, rr);
                float2 xv = *reinterpret_cast<const float2*>(xlo + d0);
                float2 ov;
                ov.x = xv.x + __sinf(rr) + oc[mt][f][0] * ilo;
                ov.y = xv.y + __cosf(rr) + oc[mt][f][1] * ilo;
                *reinterpret_cast<float2*>(olo + d0) = ov;
            }
            {
                float ang = (float)rhi * w;
                float k = rintf(ang * INV_2PI);
                float rr = fmaf(-k, PI2_HI, ang); rr = fmaf(-k, PI2_LO, rr);
                float2 xv = *reinterpret_cast<const float2*>(xhi + d0);
                float2 ov;
                ov.x = xv.x + __sinf(rr) + oc[mt][f][2] * ihi;
                ov.y = xv.y + __cosf(rr) + oc[mt][f][3] * ihi;
                *reinterpret_cast<float2*>(ohi + d0) = ov;
            }
        }
    }
}

// ================= launcher =================
extern "C" void kernel_launch(void* const* d_in, const int* in_sizes, int n_in,
                              void* d_out, int out_size)
{
    const float* x = (const float*)d_in[0];
    float* out = (float*)d_out;
    const int B = in_sizes[0] / (LSEQ * DM);

    conv_bias_kernel<<<B * LSEQ / 8, 256>>>(x);

    cudaFuncSetAttribute(tpe_flash3_kernel,
                         cudaFuncAttributeMaxDynamicSharedMemorySize, SMEM_BYTES);
    tpe_flash3_kernel<<<dim3(LSEQ / TM, B), NTHR, SMEM_BYTES>>>(x, out);
}